// round 5
// baseline (speedup 1.0000x reference)
#include <cuda_runtime.h>
#include <cstdint>

#define NN 2048
#define NBLK 148
#define NTHR 1024
#define EPSC 1e-10f
#define ITERS 50
#define KCH (NN / 128)          // 16 float4 chunks per lane per row
#define TAG_STRIDE (ITERS + 2)  // tags consumed per launch

// ---------------- device scratch (static, per harness rules) ---------------
__device__ float g_W[(size_t)NN * NN];   // W[i][j] = exp(-|s_i - a_j|)
__device__ float g_WT[(size_t)NN * NN];  // transpose
__device__ float g_lab[NN], g_s[NN];
__device__ float g_E[NN], g_Einv[NN], g_F[NN], g_Finv[NN];
__device__ float g_disc[NN];
__device__ float g_part0[NN];            // idcg partials (setup, barrier-synced)
__device__ unsigned long long g_tu[NN];  // tagged u
__device__ unsigned long long g_tv[NN];  // tagged v
__device__ unsigned long long g_tp[NN];  // tagged dcg partials
__device__ float g_idcg;
__device__ unsigned g_arrive = 0;
__device__ unsigned g_gen = 0;
__device__ unsigned g_base = 0;          // tag base, advances each launch

// ---------------- scoped atomics (no CCTL.IVALL — preserve L1D) ------------
__device__ __forceinline__ unsigned ld_acq(const unsigned* p) {
    unsigned v;
    asm volatile("ld.acquire.gpu.u32 %0, [%1];" : "=r"(v) : "l"(p) : "memory");
    return v;
}
__device__ __forceinline__ void st_rel(unsigned* p, unsigned v) {
    asm volatile("st.release.gpu.u32 [%0], %1;" :: "l"(p), "r"(v) : "memory");
}
__device__ __forceinline__ void st_rlx(unsigned* p, unsigned v) {
    asm volatile("st.relaxed.gpu.u32 [%0], %1;" :: "l"(p), "r"(v) : "memory");
}
__device__ __forceinline__ unsigned atom_add_rel(unsigned* p, unsigned v) {
    unsigned o;
    asm volatile("atom.add.release.gpu.u32 %0, [%1], %2;"
                 : "=r"(o) : "l"(p), "r"(v) : "memory");
    return o;
}

// Setup-only grid barrier (4 uses). Fence-free, replay-safe.
__device__ __forceinline__ void grid_sync(unsigned& gen) {
    __syncthreads();
    if (threadIdx.x == 0) {
        gen++;
        unsigned prev = atom_add_rel(&g_arrive, 1u);
        if (prev == NBLK - 1) {
            st_rlx(&g_arrive, 0u);
            st_rel(&g_gen, gen);
        } else {
            while (ld_acq(&g_gen) != gen) { }
        }
    }
    __syncthreads();
}

// ---------------- tagged dataflow publish / consume -------------------------
__device__ __forceinline__ void pub(unsigned long long* p, float v, unsigned tag) {
    unsigned long long x =
        ((unsigned long long)tag << 32) | (unsigned long long)__float_as_uint(v);
    asm volatile("st.relaxed.gpu.u64 [%0], %1;" :: "l"(p), "l"(x) : "memory");
}
__device__ __forceinline__ float waitv(const unsigned long long* p, unsigned tag) {
    unsigned long long x;
    do {
        asm volatile("ld.relaxed.gpu.u64 %0, [%1];" : "=l"(x) : "l"(p) : "memory");
    } while ((unsigned)(x >> 32) != tag);
    return __uint_as_float((unsigned)x);
}

__device__ __forceinline__ float warp_sum(float v) {
    #pragma unroll
    for (int o = 16; o; o >>= 1) v += __shfl_xor_sync(0xffffffffu, v, o);
    return v;
}

// warp dot of one 2048-float row with smem vector; 4 independent accumulators.
// STREAM rows use __ldcg so they never evict the L1-resident cached rows.
template <bool STREAM>
__device__ __forceinline__ float dot_row(const float* __restrict__ row,
                                         const float* __restrict__ sv, int lane) {
    const float4* r4 = reinterpret_cast<const float4*>(row);
    const float4* s4 = reinterpret_cast<const float4*>(sv);
    float a0 = 0.f, a1 = 0.f, a2 = 0.f, a3 = 0.f;
    #pragma unroll
    for (int k = 0; k < KCH; k++) {
        float4 w = STREAM ? __ldcg(r4 + lane + 32 * k) : r4[lane + 32 * k];
        float4 v = s4[lane + 32 * k];
        a0 = fmaf(w.x, v.x, a0);
        a1 = fmaf(w.y, v.y, a1);
        a2 = fmaf(w.z, v.z, a2);
        a3 = fmaf(w.w, v.w, a3);
    }
    return warp_sum((a0 + a1) + (a2 + a3));
}

__global__ void __launch_bounds__(NTHR, 1)
softndcg_kernel(const float* __restrict__ y_pred,
                const float* __restrict__ y_true,
                float* __restrict__ out) {
    __shared__ __align__(16) float spool[NN];  // aliased: staging / reduce / tile

    const int tid  = threadIdx.x;
    const int lane = tid & 31;
    const int warp = tid >> 5;
    const int bid  = blockIdx.x;
    const int gtid = bid * NTHR + tid;
    const int myrow = bid + NBLK * warp;       // this warp's owned row (or >= NN)

    unsigned gen = (tid == 0) ? ld_acq(&g_gen) : 0u;   // replay-safe barrier gen
    const unsigned bt = __ldcg(&g_base);               // replay-safe tag base

    // ---- Phase A: elementwise precompute -----------------------------------
    if (gtid < NN) {
        float a = y_pred[gtid];
        float e = expf(a);
        g_E[gtid]    = e;
        g_Einv[gtid] = 1.0f / e;
        g_lab[gtid]  = exp2f(y_true[gtid]) - 1.0f;
        g_disc[gtid] = log2f((float)gtid + 2.0f);
    }
    grid_sync(gen);

    // ---- Phase B: ranks (descending, stable) -------------------------------
    if (myrow < NN) {
        float ai = y_pred[myrow];
        float li = g_lab[myrow];
        int ca = 0, cl = 0;
        for (int j = lane; j < NN; j += 32) {
            float aj = y_pred[j];
            ca += (aj > ai) || (aj == ai && j < myrow);
            float lj = g_lab[j];
            cl += (lj > li) || (lj == li && j < myrow);
        }
        #pragma unroll
        for (int o = 16; o; o >>= 1) {
            ca += __shfl_xor_sync(0xffffffffu, ca, o);
            cl += __shfl_xor_sync(0xffffffffu, cl, o);
        }
        if (lane == 0) {
            g_s[ca]       = ai;               // descending-sorted scores
            g_part0[myrow] = li / g_disc[cl]; // idcg contribution
        }
    }
    grid_sync(gen);

    // ---- Phase C: F = exp(s); CTA0 reduces idcg ----------------------------
    if (gtid < NN) {
        float f = expf(g_s[gtid]);
        g_F[gtid]    = f;
        g_Finv[gtid] = 1.0f / f;
    }
    if (bid == 0) {
        spool[tid] = g_part0[tid] + g_part0[tid + NTHR];
        __syncthreads();
        #pragma unroll
        for (int s2 = NTHR / 2; s2 > 0; s2 >>= 1) {
            if (tid < s2) spool[tid] += spool[tid + s2];
            __syncthreads();
        }
        if (tid == 0) g_idcg = spool[0];
    }
    grid_sync(gen);

    // ---- Phase D: build W and WT (exp-free: min of exp ratios) -------------
    {
        float (*tile)[33] = reinterpret_cast<float (*)[33]>(spool);
        const int ty = warp, tx = lane;
        const int TPD = NN / 32;
        for (int t = bid; t < TPD * TPD; t += NBLK) {
            int ti = (t / TPD) * 32;
            int tj = (t % TPD) * 32;
            int i = ti + ty, j = tj + tx;
            float w = fminf(g_E[j] * g_Finv[i], g_F[i] * g_Einv[j]);
            g_W[(size_t)i * NN + j] = w;
            tile[ty][tx] = w;
            __syncthreads();
            g_WT[(size_t)(tj + ty) * NN + (ti + tx)] = tile[tx][ty];
            __syncthreads();
        }
    }
    grid_sync(gen);

    // ---- Phase E: u0 = 1/rowsum(W) -> publish u tag bt+1 -------------------
    for (int i = tid; i < NN; i += NTHR) spool[i] = 1.0f;
    __syncthreads();
    {
        float vcur = 1.0f;  // this warp's v[myrow], carried in registers
        if (myrow < NN) {
            float acc = (warp < 13)
                ? dot_row<false>(g_W + (size_t)myrow * NN, spool, lane)
                : dot_row<true >(g_W + (size_t)myrow * NN, spool, lane);
            if (lane == 0) pub(&g_tu[myrow], 1.0f / acc, bt + 1);
        }

        // ---- Sinkhorn: 50 iterations, pure dataflow (no barriers) ----------
        float ucur = 0.f;  // carried u[myrow] (valid in lane 0)
        for (int t = 1; t <= ITERS; t++) {
            // col step: v <- v / clip(v * (W^T u), EPS), consume u tag bt+t
            for (int i = tid; i < NN; i += NTHR) spool[i] = waitv(&g_tu[i], bt + t);
            __syncthreads();
            if (myrow < NN) {
                if (lane == 0 && t == 1) ucur = spool[myrow];
                float acc = (warp < 13)
                    ? dot_row<false>(g_WT + (size_t)myrow * NN, spool, lane)
                    : dot_row<true >(g_WT + (size_t)myrow * NN, spool, lane);
                if (lane == 0) {
                    vcur = vcur / fmaxf(vcur * acc, EPSC);
                    pub(&g_tv[myrow], vcur, bt + t);
                }
            }
            __syncthreads();  // protect spool before restage

            // row step: u <- u / clip(u * (W v), EPS), consume v tag bt+t
            for (int i = tid; i < NN; i += NTHR) spool[i] = waitv(&g_tv[i], bt + t);
            __syncthreads();
            if (myrow < NN) {
                float acc = (warp < 13)
                    ? dot_row<false>(g_W + (size_t)myrow * NN, spool, lane)
                    : dot_row<true >(g_W + (size_t)myrow * NN, spool, lane);
                if (lane == 0) {
                    ucur = ucur / fmaxf(ucur * acc, EPSC);
                    pub(&g_tu[myrow], ucur, bt + t + 1);
                }
            }
            __syncthreads();
        }

        // ---- Final: dcg_i = u_i * (W (v .* lab))_i / disc_i ----------------
        for (int i = tid; i < NN; i += NTHR)
            spool[i] = waitv(&g_tv[i], bt + ITERS) * g_lab[i];
        __syncthreads();
        if (myrow < NN) {
            float acc = (warp < 13)
                ? dot_row<false>(g_W + (size_t)myrow * NN, spool, lane)
                : dot_row<true >(g_W + (size_t)myrow * NN, spool, lane);
            if (lane == 0)
                pub(&g_tp[myrow], ucur * acc / g_disc[myrow], bt + ITERS + 1);
        }
        __syncthreads();
    }

    // ---- CTA0 gathers tagged partials, reduces, writes output --------------
    if (bid == 0) {
        float v = waitv(&g_tp[tid], bt + ITERS + 1)
                + waitv(&g_tp[tid + NTHR], bt + ITERS + 1);
        spool[tid] = v;
        __syncthreads();
        #pragma unroll
        for (int s2 = NTHR / 2; s2 > 0; s2 >>= 1) {
            if (tid < s2) spool[tid] += spool[tid + s2];
            __syncthreads();
        }
        if (tid == 0) {
            out[0] = 1.0f - spool[0] / g_idcg;
            st_rlx(&g_base, bt + TAG_STRIDE);  // advance tags for next replay
        }
    }
}

extern "C" void kernel_launch(void* const* d_in, const int* in_sizes, int n_in,
                              void* d_out, int out_size) {
    const float* y_pred = (const float*)d_in[0];
    const float* y_true = (const float*)d_in[1];
    float* out = (float*)d_out;
    (void)in_sizes; (void)n_in; (void)out_size;
    softndcg_kernel<<<NBLK, NTHR>>>(y_pred, y_true, out);
}